// round 1
// baseline (speedup 1.0000x reference)
#include <cuda_runtime.h>
#include <math.h>

// ---------------------------------------------------------------------------
// SimpleVQAutoEncoder on GB300 — fp32 SIMT baseline
//
// Pipeline:
//   K1: conv1(1->16,3x3,SAME) + maxpool2 + gelu        -> g_h1 [32,16,128,128]
//   K2: conv2(16->32,3x3,SAME) + maxpool2              -> g_h2 [32,32,64,64]
//   K3: VQ argmin over 512 codes, gather, commit parts -> g_hq, indices, g_part
//   K4: up2 + conv d1(32->16) (parity-folded) + gelu   -> g_gg [32,16,128,128]
//   K5: up2 + conv d2(16->1)  (parity-folded) + clip   -> out y
//   K6: reduce commit-loss partials                    -> out[last]
//   K0: setup (codebook half-norms, parity-folded decoder weights)
//
// Output layout (float32): [ y (32*1*256*256) | indices (32*64*64) | loss (1) ]
// ---------------------------------------------------------------------------

#define Y_ELEMS   2097152   // 32*256*256
#define IDX_OFF   2097152
#define IDX_ELEMS 131072    // 32*64*64
#define LOSS_OFF  2228224

// Intermediates (device globals: no allocation allowed)
__device__ float g_h1[32 * 16 * 128 * 128];   // 33.5 MB
__device__ float g_h2[32 * 32 * 64 * 64];     // 16.8 MB
__device__ float g_hq[32 * 32 * 64 * 64];     // 16.8 MB
__device__ float g_gg[32 * 16 * 128 * 128];   // 33.5 MB
__device__ float g_cnh[512];                  // 0.5*||codebook_k||^2
__device__ float g_Wf1[4 * 16 * 32 * 4];      // folded d1 weights [parity][c][ci][uv]
__device__ float g_Wf2[4 * 16 * 4];           // folded d2 weights [parity][ci][uv]
__device__ float g_part[256];                 // commit-loss partials per VQ block

// ---------------------------------------------------------------------------
// K0: setup — fold upsample+conv weights per output parity, codebook norms.
// Nearest-up2 means the 3x3 taps at output (y,x) read only a 2x2 hq patch:
//   rows used: ra=(y-1)>>1 (tap set depends on y parity), rb=(y+1)>>1
//   parity 0 (even): dy0 -> ra ; dy1,dy2 -> rb
//   parity 1 (odd) : dy0,dy1 -> ra ; dy2 -> rb
// Same for columns. Folded weight = sum of taps mapping to each corner.
// ---------------------------------------------------------------------------
__global__ void __launch_bounds__(256) k0_setup(const float* __restrict__ cb,
                                                const float* __restrict__ d1w,
                                                const float* __restrict__ d2w) {
    int t = blockIdx.x * 256 + threadIdx.x;
    if (t < 8192) {
        // Wf1 entry: uv in [0,4), ci in [0,32), c in [0,16), p in [0,4)
        int uv = t & 3, ci = (t >> 2) & 31, c = (t >> 7) & 15, p = t >> 11;
        int py = p >> 1, px = p & 1, u = uv >> 1, v = uv & 1;
        float s = 0.f;
        #pragma unroll
        for (int dy = 0; dy < 3; ++dy) {
            int ug = (py == 0) ? (dy >= 1) : (dy >= 2);
            if (ug != u) continue;
            #pragma unroll
            for (int dx = 0; dx < 3; ++dx) {
                int vg = (px == 0) ? (dx >= 1) : (dx >= 2);
                if (vg != v) continue;
                s += d1w[((c * 32 + ci) * 3 + dy) * 3 + dx];
            }
        }
        g_Wf1[((p * 16 + c) * 32 + ci) * 4 + uv] = s;
    } else if (t < 8704) {
        int k = t - 8192;
        float s = 0.f;
        #pragma unroll
        for (int c = 0; c < 32; ++c) { float v = cb[k * 32 + c]; s = fmaf(v, v, s); }
        g_cnh[k] = 0.5f * s;
    } else if (t < 8960) {
        int e = t - 8704;
        int uv = e & 3, ci = (e >> 2) & 15, p = e >> 6;
        int py = p >> 1, px = p & 1, u = uv >> 1, v = uv & 1;
        float s = 0.f;
        #pragma unroll
        for (int dy = 0; dy < 3; ++dy) {
            int ug = (py == 0) ? (dy >= 1) : (dy >= 2);
            if (ug != u) continue;
            #pragma unroll
            for (int dx = 0; dx < 3; ++dx) {
                int vg = (px == 0) ? (dx >= 1) : (dx >= 2);
                if (vg != v) continue;
                s += d2w[ci * 9 + dy * 3 + dx];
            }
        }
        g_Wf2[(p * 16 + ci) * 4 + uv] = s;
    }
}

// ---------------------------------------------------------------------------
// K1: conv1 + maxpool2 + exact gelu. Thread = (b, i, j) pooled pixel, 16 chans.
// ---------------------------------------------------------------------------
__global__ void __launch_bounds__(256) k1_conv1(const float* __restrict__ x,
                                                const float* __restrict__ w,
                                                const float* __restrict__ bias) {
    __shared__ float sw[144];
    __shared__ float sb[16];
    int tid = threadIdx.x;
    if (tid < 144) sw[tid] = __ldg(w + tid);
    if (tid < 16)  sb[tid] = __ldg(bias + tid);
    __syncthreads();

    int lin = blockIdx.x * 256 + tid;
    int j = lin & 127, i = (lin >> 7) & 127, b = lin >> 14;
    const float* xb = x + (b << 16);  // 256*256 per image

    float xv[4][4];
    #pragma unroll
    for (int r = 0; r < 4; ++r) {
        int ry = 2 * i - 1 + r;
        bool rok = (unsigned)ry < 256u;
        #pragma unroll
        for (int cc = 0; cc < 4; ++cc) {
            int cx = 2 * j - 1 + cc;
            xv[r][cc] = (rok && (unsigned)cx < 256u) ? __ldg(xb + ry * 256 + cx) : 0.f;
        }
    }

    #pragma unroll
    for (int c = 0; c < 16; ++c) {
        float wv[9];
        #pragma unroll
        for (int k = 0; k < 9; ++k) wv[k] = sw[c * 9 + k];
        float m = -1e30f;
        #pragma unroll
        for (int py = 0; py < 2; ++py) {
            #pragma unroll
            for (int px = 0; px < 2; ++px) {
                float s = 0.f;
                #pragma unroll
                for (int dy = 0; dy < 3; ++dy)
                    #pragma unroll
                    for (int dx = 0; dx < 3; ++dx)
                        s = fmaf(wv[dy * 3 + dx], xv[py + dy][px + dx], s);
                m = fmaxf(m, s);
            }
        }
        m += sb[c];
        g_h1[((b * 16 + c) << 14) + (i << 7) + j] = m * normcdff(m);  // exact gelu
    }
}

// ---------------------------------------------------------------------------
// K2: conv2(16->32) + maxpool2. Thread = (b, i, j) pooled pixel, 32 chans.
// ---------------------------------------------------------------------------
__global__ void __launch_bounds__(256) k2_conv2(const float* __restrict__ w,
                                                const float* __restrict__ bias) {
    __shared__ float sw[4608];
    __shared__ float sb[32];
    int tid = threadIdx.x;
    for (int t = tid; t < 4608; t += 256) sw[t] = __ldg(w + t);
    if (tid < 32) sb[tid] = __ldg(bias + tid);
    __syncthreads();

    int lin = blockIdx.x * 256 + tid;
    int j = lin & 63, i = (lin >> 6) & 63, b = lin >> 12;

    float best[32];
    #pragma unroll
    for (int c = 0; c < 32; ++c) best[c] = -1e30f;

    #pragma unroll 1
    for (int p = 0; p < 4; ++p) {
        int py = p >> 1, px = p & 1;
        float acc[32];
        #pragma unroll
        for (int c = 0; c < 32; ++c) acc[c] = 0.f;

        #pragma unroll 1
        for (int ci = 0; ci < 16; ++ci) {
            const float* src = g_h1 + ((b * 16 + ci) << 14);
            int wbase = ci * 9;
            #pragma unroll
            for (int dy = 0; dy < 3; ++dy) {
                int ry = 2 * i + py - 1 + dy;
                bool rok = (unsigned)ry < 128u;
                #pragma unroll
                for (int dx = 0; dx < 3; ++dx) {
                    int cx = 2 * j + px - 1 + dx;
                    float v = (rok && (unsigned)cx < 128u) ? src[(ry << 7) + cx] : 0.f;
                    int woff = wbase + dy * 3 + dx;
                    #pragma unroll
                    for (int c = 0; c < 32; ++c)
                        acc[c] = fmaf(sw[c * 144 + woff], v, acc[c]);
                }
            }
        }
        #pragma unroll
        for (int c = 0; c < 32; ++c) best[c] = fmaxf(best[c], acc[c]);
    }
    #pragma unroll
    for (int c = 0; c < 32; ++c)
        g_h2[((b * 32 + c) << 12) + (i << 6) + j] = best[c] + sb[c];
}

// ---------------------------------------------------------------------------
// K3: vector quantize. 256 threads/block, 2 tokens/thread, 512 tokens/block.
// score = f.c - 0.5||c||^2 maximized  ==  argmin of full squared distance.
// Strict '>' keeps the FIRST max -> matches jnp.argmin first-tie semantics.
// ---------------------------------------------------------------------------
__global__ void __launch_bounds__(256) k3_vq(const float* __restrict__ cb,
                                             float* __restrict__ out) {
    int tid = threadIdx.x, blk = blockIdx.x;
    int n0 = blk << 9;
    int t0 = n0 + tid, t1 = t0 + 256;
    int b = n0 >> 12;                 // 4096 tokens per batch image
    int ij0 = t0 & 4095, ij1 = t1 & 4095;

    const float* h2b = g_h2 + (b << 17);   // b*32*4096
    float f0[32], f1[32];
    #pragma unroll
    for (int c = 0; c < 32; ++c) {
        f0[c] = h2b[(c << 12) + ij0];
        f1[c] = h2b[(c << 12) + ij1];
    }

    float best0 = -1e30f, best1 = -1e30f;
    int bk0 = 0, bk1 = 0;
    const float4* cb4 = (const float4*)cb;

    #pragma unroll 1
    for (int k = 0; k < 512; ++k) {
        float s0 = 0.f, s1 = 0.f;
        #pragma unroll
        for (int q = 0; q < 8; ++q) {
            float4 cv = __ldg(cb4 + k * 8 + q);   // uniform across warp -> broadcast
            s0 = fmaf(cv.x, f0[q * 4 + 0], s0);
            s0 = fmaf(cv.y, f0[q * 4 + 1], s0);
            s0 = fmaf(cv.z, f0[q * 4 + 2], s0);
            s0 = fmaf(cv.w, f0[q * 4 + 3], s0);
            s1 = fmaf(cv.x, f1[q * 4 + 0], s1);
            s1 = fmaf(cv.y, f1[q * 4 + 1], s1);
            s1 = fmaf(cv.z, f1[q * 4 + 2], s1);
            s1 = fmaf(cv.w, f1[q * 4 + 3], s1);
        }
        float cn = g_cnh[k];
        float v0 = s0 - cn, v1 = s1 - cn;
        if (v0 > best0) { best0 = v0; bk0 = k; }
        if (v1 > best1) { best1 = v1; bk1 = k; }
    }

    out[IDX_OFF + t0] = (float)bk0;
    out[IDX_OFF + t1] = (float)bk1;

    float part = 0.f;
    #pragma unroll
    for (int c = 0; c < 32; ++c) {
        float q0 = __ldg(cb + bk0 * 32 + c);
        float d0 = q0 - f0[c];
        part = fmaf(d0, d0, part);
        g_hq[(b << 17) + (c << 12) + ij0] = q0;
        float q1 = __ldg(cb + bk1 * 32 + c);
        float d1 = q1 - f1[c];
        part = fmaf(d1, d1, part);
        g_hq[(b << 17) + (c << 12) + ij1] = q1;
    }

    // deterministic block reduction
    __shared__ float ws[8];
    #pragma unroll
    for (int o = 16; o > 0; o >>= 1)
        part += __shfl_down_sync(0xffffffffu, part, o);
    if ((tid & 31) == 0) ws[tid >> 5] = part;
    __syncthreads();
    if (tid == 0) {
        float s = 0.f;
        #pragma unroll
        for (int q = 0; q < 8; ++q) s += ws[q];
        g_part[blk] = s;
    }
}

// ---------------------------------------------------------------------------
// K4: up2 + conv d1 (parity-folded 2x2) + gelu. Thread = (b,y,x), 16 chans.
// ---------------------------------------------------------------------------
__global__ void __launch_bounds__(256) k4_dec1(const float* __restrict__ bias) {
    __shared__ float sW[8192];
    __shared__ float sb[16];
    int tid = threadIdx.x;
    for (int t = tid; t < 8192; t += 256) sW[t] = g_Wf1[t];
    if (tid < 16) sb[tid] = __ldg(bias + tid);
    __syncthreads();

    int lin = blockIdx.x * 256 + tid;
    int x = lin & 127, y = (lin >> 7) & 127, b = lin >> 14;
    int py = y & 1, px = x & 1, p = py * 2 + px;
    int ra = (y == 0) ? -1 : ((y - 1) >> 1);
    int rb = (y + 1) >> 1;
    int ca = (x == 0) ? -1 : ((x - 1) >> 1);
    int cc = (x + 1) >> 1;
    bool raok = ra >= 0, rbok = rb < 64, caok = ca >= 0, cbok = cc < 64;

    float acc[16];
    #pragma unroll
    for (int c = 0; c < 16; ++c) acc[c] = 0.f;

    #pragma unroll 1
    for (int ci = 0; ci < 32; ++ci) {
        const float* base = g_hq + (b << 17) + (ci << 12);
        float v00 = (raok && caok) ? base[(ra << 6) + ca] : 0.f;
        float v01 = (raok && cbok) ? base[(ra << 6) + cc] : 0.f;
        float v10 = (rbok && caok) ? base[(rb << 6) + ca] : 0.f;
        float v11 = (rbok && cbok) ? base[(rb << 6) + cc] : 0.f;
        int wb = (p * 16 * 32 + ci) * 4;
        #pragma unroll
        for (int c = 0; c < 16; ++c) {
            const float* wp = sW + wb + c * 128;
            acc[c] = fmaf(wp[0], v00, acc[c]);
            acc[c] = fmaf(wp[1], v01, acc[c]);
            acc[c] = fmaf(wp[2], v10, acc[c]);
            acc[c] = fmaf(wp[3], v11, acc[c]);
        }
    }
    #pragma unroll
    for (int c = 0; c < 16; ++c) {
        float m = acc[c] + sb[c];
        g_gg[((b * 16 + c) << 14) + (y << 7) + x] = m * normcdff(m);
    }
}

// ---------------------------------------------------------------------------
// K5: up2 + conv d2 (parity-folded) + clip. Thread = (b,y,x) in 256x256.
// ---------------------------------------------------------------------------
__global__ void __launch_bounds__(256) k5_dec2(const float* __restrict__ bias,
                                               float* __restrict__ out) {
    __shared__ float sW[256];
    int tid = threadIdx.x;
    sW[tid] = g_Wf2[tid];
    __syncthreads();

    int lin = blockIdx.x * 256 + tid;
    int x = lin & 255, y = (lin >> 8) & 255, b = lin >> 16;
    int py = y & 1, px = x & 1, p = py * 2 + px;
    int ra = (y == 0) ? -1 : ((y - 1) >> 1);
    int rb = (y + 1) >> 1;
    int ca = (x == 0) ? -1 : ((x - 1) >> 1);
    int cc = (x + 1) >> 1;
    bool raok = ra >= 0, rbok = rb < 128, caok = ca >= 0, cbok = cc < 128;

    float s = 0.f;
    #pragma unroll
    for (int ci = 0; ci < 16; ++ci) {
        const float* base = g_gg + ((b * 16 + ci) << 14);
        float v00 = (raok && caok) ? base[(ra << 7) + ca] : 0.f;
        float v01 = (raok && cbok) ? base[(ra << 7) + cc] : 0.f;
        float v10 = (rbok && caok) ? base[(rb << 7) + ca] : 0.f;
        float v11 = (rbok && cbok) ? base[(rb << 7) + cc] : 0.f;
        const float* wp = sW + (p * 16 + ci) * 4;
        s = fmaf(wp[0], v00, s);
        s = fmaf(wp[1], v01, s);
        s = fmaf(wp[2], v10, s);
        s = fmaf(wp[3], v11, s);
    }
    s += __ldg(bias);
    out[(b << 16) + (y << 8) + x] = fminf(fmaxf(s, -1.f), 1.f);
}

// ---------------------------------------------------------------------------
// K6: final commit-loss reduction (deterministic tree).
// ---------------------------------------------------------------------------
__global__ void __launch_bounds__(256) k6_loss(float* __restrict__ out) {
    __shared__ float sm[256];
    int tid = threadIdx.x;
    sm[tid] = g_part[tid];
    __syncthreads();
    #pragma unroll
    for (int o = 128; o > 0; o >>= 1) {
        if (tid < o) sm[tid] += sm[tid + o];
        __syncthreads();
    }
    if (tid == 0) out[LOSS_OFF] = sm[0] * (1.0f / 4194304.0f);  // mean over N*C
}

// ---------------------------------------------------------------------------
extern "C" void kernel_launch(void* const* d_in, const int* in_sizes, int n_in,
                              void* d_out, int out_size) {
    const float* x   = (const float*)d_in[0];
    const float* e1w = (const float*)d_in[1];
    const float* e1b = (const float*)d_in[2];
    const float* e2w = (const float*)d_in[3];
    const float* e2b = (const float*)d_in[4];
    const float* cb  = (const float*)d_in[5];
    const float* d1w = (const float*)d_in[6];
    const float* d1b = (const float*)d_in[7];
    const float* d2w = (const float*)d_in[8];
    const float* d2b = (const float*)d_in[9];
    float* out = (float*)d_out;

    k0_setup<<<35, 256>>>(cb, d1w, d2w);
    k1_conv1<<<2048, 256>>>(x, e1w, e1b);
    k2_conv2<<<512, 256>>>(e2w, e2b);
    k3_vq<<<256, 256>>>(cb, out);
    k4_dec1<<<2048, 256>>>(d1b);
    k5_dec2<<<8192, 256>>>(d2b, out);
    k6_loss<<<1, 256>>>(out);
}

// round 2
// speedup vs baseline: 1.9578x; 1.9578x over previous
#include <cuda_runtime.h>
#include <math.h>

// ---------------------------------------------------------------------------
// SimpleVQAutoEncoder on GB300 — fp32 SIMT + packed fma.rn.f32x2 (FFMA2)
//
//   K0: setup (codebook transpose+half-norms, parity-folded decoder weights)
//   K1: conv1(1->16,3x3,SAME) + maxpool2 + gelu        -> g_h1 [32,16,128,128]
//   K2: conv2(16->32,3x3,SAME) + maxpool2 (FFMA2)      -> g_h2 [32,32,64,64]
//   K3: VQ argmin 512 codes (code-pair FFMA2), gather  -> g_hq, indices, g_part
//   K4: up2 + conv d1(32->16) folded (FFMA2) + gelu    -> g_gg [32,16,128,128]
//   K5: up2 + conv d2(16->1)  folded + clip            -> out y
//   K6: reduce commit-loss partials                    -> out[last]
//
// Output layout (float32): [ y (32*256*256) | indices (32*64*64) | loss (1) ]
// ---------------------------------------------------------------------------

#define IDX_OFF   2097152
#define LOSS_OFF  2228224

typedef unsigned long long u64;

__device__ __forceinline__ u64 ffma2(u64 a, u64 b, u64 c) {
    u64 d;
    asm("fma.rn.f32x2 %0, %1, %2, %3;" : "=l"(d) : "l"(a), "l"(b), "l"(c));
    return d;
}
__device__ __forceinline__ u64 packff(float lo, float hi) {
    u64 d;
    asm("mov.b64 %0, {%1, %2};" : "=l"(d) : "f"(lo), "f"(hi));
    return d;
}
__device__ __forceinline__ float2 unpackff(u64 v) {
    float lo, hi;
    asm("mov.b64 {%0, %1}, %2;" : "=f"(lo), "=f"(hi) : "l"(v));
    return make_float2(lo, hi);
}

// Intermediates (device globals: no allocation allowed)
__device__ float g_h1[32 * 16 * 128 * 128];   // 33.5 MB
__device__ float g_h2[32 * 32 * 64 * 64];     // 16.8 MB
__device__ float g_hq[32 * 32 * 64 * 64];     // 16.8 MB
__device__ float g_gg[32 * 16 * 128 * 128];   // 33.5 MB
__device__ float g_cbT[32 * 512];             // transposed codebook [c][k]
__device__ float g_cnh[512];                  // 0.5*||codebook_k||^2
__device__ float g_Wf1t[4 * 32 * 4 * 16];     // folded d1 [p][ci][uv][c]
__device__ float g_Wf2[4 * 16 * 4];           // folded d2 [p][ci][uv]
__device__ float g_part[512];                 // commit-loss partials

// ---------------------------------------------------------------------------
// K0: setup.
// Nearest-up2 folding: output (y,x) reads a 2x2 hq patch; 3x3 taps collapse
// per output parity (py,px) onto the 4 corners.
// ---------------------------------------------------------------------------
__global__ void __launch_bounds__(256) k0_setup(const float* __restrict__ cb,
                                                const float* __restrict__ d1w,
                                                const float* __restrict__ d2w) {
    int t = blockIdx.x * 256 + threadIdx.x;
    if (t < 8192) {
        // g_Wf1t[((p*32+ci)*4+uv)*16 + c]
        int c = t & 15, uv = (t >> 4) & 3, ci = (t >> 6) & 31, p = t >> 11;
        int py = p >> 1, px = p & 1, u = uv >> 1, v = uv & 1;
        float s = 0.f;
        #pragma unroll
        for (int dy = 0; dy < 3; ++dy) {
            int ug = (py == 0) ? (dy >= 1) : (dy >= 2);
            if (ug != u) continue;
            #pragma unroll
            for (int dx = 0; dx < 3; ++dx) {
                int vg = (px == 0) ? (dx >= 1) : (dx >= 2);
                if (vg != v) continue;
                s += d1w[((c * 32 + ci) * 3 + dy) * 3 + dx];
            }
        }
        g_Wf1t[t] = s;
    } else if (t < 8704) {
        int k = t - 8192;
        float s = 0.f;
        #pragma unroll
        for (int c = 0; c < 32; ++c) { float v = cb[k * 32 + c]; s = fmaf(v, v, s); }
        g_cnh[k] = 0.5f * s;
    } else if (t < 8960) {
        int e = t - 8704;
        int uv = e & 3, ci = (e >> 2) & 15, p = e >> 6;
        int py = p >> 1, px = p & 1, u = uv >> 1, v = uv & 1;
        float s = 0.f;
        #pragma unroll
        for (int dy = 0; dy < 3; ++dy) {
            int ug = (py == 0) ? (dy >= 1) : (dy >= 2);
            if (ug != u) continue;
            #pragma unroll
            for (int dx = 0; dx < 3; ++dx) {
                int vg = (px == 0) ? (dx >= 1) : (dx >= 2);
                if (vg != v) continue;
                s += d2w[ci * 9 + dy * 3 + dx];
            }
        }
        g_Wf2[(p * 16 + ci) * 4 + uv] = s;
    } else if (t < 25344) {
        int e = t - 8960;
        int c = e >> 9, k = e & 511;
        g_cbT[c * 512 + k] = cb[k * 32 + c];
    }
}

// ---------------------------------------------------------------------------
// K1: conv1 + maxpool2 + exact gelu. Thread = (b, i, j) pooled pixel, 16 ch.
// ---------------------------------------------------------------------------
__global__ void __launch_bounds__(256) k1_conv1(const float* __restrict__ x,
                                                const float* __restrict__ w,
                                                const float* __restrict__ bias) {
    __shared__ float sw[144];
    __shared__ float sb[16];
    int tid = threadIdx.x;
    if (tid < 144) sw[tid] = __ldg(w + tid);
    if (tid < 16)  sb[tid] = __ldg(bias + tid);
    __syncthreads();

    int lin = blockIdx.x * 256 + tid;
    int j = lin & 127, i = (lin >> 7) & 127, b = lin >> 14;
    const float* xb = x + (b << 16);

    float xv[4][4];
    #pragma unroll
    for (int r = 0; r < 4; ++r) {
        int ry = 2 * i - 1 + r;
        bool rok = (unsigned)ry < 256u;
        #pragma unroll
        for (int cc = 0; cc < 4; ++cc) {
            int cx = 2 * j - 1 + cc;
            xv[r][cc] = (rok && (unsigned)cx < 256u) ? __ldg(xb + ry * 256 + cx) : 0.f;
        }
    }

    #pragma unroll
    for (int c = 0; c < 16; ++c) {
        float wv[9];
        #pragma unroll
        for (int k = 0; k < 9; ++k) wv[k] = sw[c * 9 + k];
        float m = -1e30f;
        #pragma unroll
        for (int py = 0; py < 2; ++py)
            #pragma unroll
            for (int px = 0; px < 2; ++px) {
                float s = 0.f;
                #pragma unroll
                for (int dy = 0; dy < 3; ++dy)
                    #pragma unroll
                    for (int dx = 0; dx < 3; ++dx)
                        s = fmaf(wv[dy * 3 + dx], xv[py + dy][px + dx], s);
                m = fmaxf(m, s);
            }
        m += sb[c];
        g_h1[((b * 16 + c) << 14) + (i << 7) + j] = m * normcdff(m);
    }
}

// ---------------------------------------------------------------------------
// K2: conv2(16->32) + maxpool2, FFMA2 on channel pairs.
// Thread = (b, half, i, j): 16 output channels, 4x4 patch reused across the
// 4 pool quadrants. half is uniform per block (bit 12 of lin).
// ---------------------------------------------------------------------------
__global__ void __launch_bounds__(256) k2_conv2(const float* __restrict__ w,
                                                const float* __restrict__ bias) {
    __shared__ __align__(16) float swt[2304];  // [ci*9+tap][16c]
    __shared__ float sb[16];
    int tid = threadIdx.x;
    int lin = blockIdx.x * 256 + tid;
    int j = lin & 63, i = (lin >> 6) & 63, half = (lin >> 12) & 1, b = lin >> 13;

    for (int t = tid; t < 2304; t += 256) {
        int ci = t / 144, r = t - ci * 144;
        int tap = r >> 4, c = r & 15;
        swt[t] = __ldg(w + (half * 16 + c) * 144 + ci * 9 + tap);
    }
    if (tid < 16) sb[tid] = __ldg(bias + half * 16 + tid);
    __syncthreads();

    // patch row/col validity (input is 128x128)
    int ry[4], cx[4];
    bool rok[4], cok[4];
    #pragma unroll
    for (int r = 0; r < 4; ++r) {
        ry[r] = 2 * i - 1 + r; rok[r] = (unsigned)ry[r] < 128u;
        cx[r] = 2 * j - 1 + r; cok[r] = (unsigned)cx[r] < 128u;
    }

    u64 acc[4][8];
    #pragma unroll
    for (int p = 0; p < 4; ++p)
        #pragma unroll
        for (int q = 0; q < 8; ++q) acc[p][q] = 0ull;

    #pragma unroll 1
    for (int ci = 0; ci < 16; ++ci) {
        const float* src = g_h1 + ((b * 16 + ci) << 14);
        float patch[4][4];
        #pragma unroll
        for (int r = 0; r < 4; ++r)
            #pragma unroll
            for (int cc = 0; cc < 4; ++cc)
                patch[r][cc] = (rok[r] && cok[cc]) ? src[(ry[r] << 7) + cx[cc]] : 0.f;

        #pragma unroll
        for (int dy = 0; dy < 3; ++dy)
            #pragma unroll
            for (int dx = 0; dx < 3; ++dx) {
                const ulonglong2* W2 =
                    (const ulonglong2*)(swt + (ci * 9 + dy * 3 + dx) * 16);
                ulonglong2 wA = W2[0], wB = W2[1];
                #pragma unroll
                for (int p = 0; p < 4; ++p) {
                    float v = patch[(p >> 1) + dy][(p & 1) + dx];
                    u64 vp = packff(v, v);
                    acc[p][0] = ffma2(wA.x, vp, acc[p][0]);
                    acc[p][1] = ffma2(wA.y, vp, acc[p][1]);
                    acc[p][2] = ffma2(wB.x, vp, acc[p][2]);
                    acc[p][3] = ffma2(wB.y, vp, acc[p][3]);
                }
                const ulonglong2* W2b = W2 + 2;
                ulonglong2 wC = W2b[0], wD = W2b[1];
                #pragma unroll
                for (int p = 0; p < 4; ++p) {
                    float v = patch[(p >> 1) + dy][(p & 1) + dx];
                    u64 vp = packff(v, v);
                    acc[p][4] = ffma2(wC.x, vp, acc[p][4]);
                    acc[p][5] = ffma2(wC.y, vp, acc[p][5]);
                    acc[p][6] = ffma2(wD.x, vp, acc[p][6]);
                    acc[p][7] = ffma2(wD.y, vp, acc[p][7]);
                }
            }
    }

    float* dst = g_h2 + ((b * 32 + half * 16) << 12) + (i << 6) + j;
    #pragma unroll
    for (int q = 0; q < 8; ++q) {
        float2 m0 = unpackff(acc[0][q]);
        float2 m1 = unpackff(acc[1][q]);
        float2 m2 = unpackff(acc[2][q]);
        float2 m3 = unpackff(acc[3][q]);
        float lo = fmaxf(fmaxf(m0.x, m1.x), fmaxf(m2.x, m3.x)) + sb[2 * q];
        float hi = fmaxf(fmaxf(m0.y, m1.y), fmaxf(m2.y, m3.y)) + sb[2 * q + 1];
        dst[(2 * q) << 12]     = lo;
        dst[(2 * q + 1) << 12] = hi;
    }
}

// ---------------------------------------------------------------------------
// K3: VQ. 1 token/thread, codebook transposed [c][k] streamed via smem chunks,
// code pairs packed into f32x2 lanes. score = f.c - 0.5||c||^2 maximized.
// Ascending-k compare with strict '>' keeps first max (argmin semantics).
// ---------------------------------------------------------------------------
__global__ void __launch_bounds__(256) k3_vq(const float* __restrict__ cb,
                                             float* __restrict__ out) {
    __shared__ __align__(16) float sCb[32 * 128];  // chunk [c][128]
    __shared__ float sCn[128];
    int tid = threadIdx.x;
    int tok = blockIdx.x * 256 + tid;
    int b = tok >> 12, ij = tok & 4095;

    const float* h2b = g_h2 + (b << 17);
    float f[32];
    #pragma unroll
    for (int c = 0; c < 32; ++c) f[c] = h2b[(c << 12) + ij];

    float best = -1e30f;
    int bk = 0;

    #pragma unroll 1
    for (int ch = 0; ch < 4; ++ch) {
        __syncthreads();
        for (int t = tid; t < 4096; t += 256) {
            int c = t >> 7, kk = t & 127;
            sCb[t] = g_cbT[c * 512 + ch * 128 + kk];
        }
        if (tid < 128) sCn[tid] = g_cnh[ch * 128 + tid];
        __syncthreads();

        #pragma unroll 1
        for (int g = 0; g < 16; ++g) {
            u64 s2[4] = {0ull, 0ull, 0ull, 0ull};
            #pragma unroll
            for (int c = 0; c < 32; ++c) {
                u64 fp = packff(f[c], f[c]);
                const ulonglong2* W = (const ulonglong2*)(sCb + c * 128 + g * 8);
                ulonglong2 w0 = W[0], w1 = W[1];
                s2[0] = ffma2(w0.x, fp, s2[0]);
                s2[1] = ffma2(w0.y, fp, s2[1]);
                s2[2] = ffma2(w1.x, fp, s2[2]);
                s2[3] = ffma2(w1.y, fp, s2[3]);
            }
            int kbase = ch * 128 + g * 8;
            #pragma unroll
            for (int q = 0; q < 4; ++q) {
                float2 sv = unpackff(s2[q]);
                float v0 = sv.x - sCn[g * 8 + 2 * q];
                if (v0 > best) { best = v0; bk = kbase + 2 * q; }
                float v1 = sv.y - sCn[g * 8 + 2 * q + 1];
                if (v1 > best) { best = v1; bk = kbase + 2 * q + 1; }
            }
        }
    }

    out[IDX_OFF + tok] = (float)bk;

    float part = 0.f;
    #pragma unroll
    for (int c = 0; c < 32; ++c) {
        float qv = __ldg(cb + bk * 32 + c);
        float d = qv - f[c];
        part = fmaf(d, d, part);
        g_hq[(b << 17) + (c << 12) + ij] = qv;
    }

    __shared__ float ws[8];
    #pragma unroll
    for (int o = 16; o > 0; o >>= 1)
        part += __shfl_down_sync(0xffffffffu, part, o);
    if ((tid & 31) == 0) ws[tid >> 5] = part;
    __syncthreads();
    if (tid == 0) {
        float s = 0.f;
        #pragma unroll
        for (int q = 0; q < 8; ++q) s += ws[q];
        g_part[blockIdx.x] = s;
    }
}

// ---------------------------------------------------------------------------
// K4: up2 + conv d1 (parity-folded) + gelu, FFMA2 channel pairs.
// Thread = (b,y,x), 16 out channels.
// ---------------------------------------------------------------------------
__global__ void __launch_bounds__(256) k4_dec1(const float* __restrict__ bias) {
    __shared__ __align__(16) float sW[8192];  // [p][ci][uv][16c]
    __shared__ float sb[16];
    int tid = threadIdx.x;
    for (int t = tid; t < 8192; t += 256) sW[t] = g_Wf1t[t];
    if (tid < 16) sb[tid] = __ldg(bias + tid);
    __syncthreads();

    int lin = blockIdx.x * 256 + tid;
    int x = lin & 127, y = (lin >> 7) & 127, b = lin >> 14;
    int p = (y & 1) * 2 + (x & 1);
    int ra = (y - 1) >> 1, rb = (y + 1) >> 1;
    int ca = (x - 1) >> 1, cc = (x + 1) >> 1;
    bool raok = y > 0, rbok = rb < 64, caok = x > 0, cbok = cc < 64;

    u64 acc[8];
    #pragma unroll
    for (int q = 0; q < 8; ++q) acc[q] = 0ull;

    #pragma unroll 1
    for (int ci = 0; ci < 32; ++ci) {
        const float* base = g_hq + (b << 17) + (ci << 12);
        float v[4];
        v[0] = (raok && caok) ? base[(ra << 6) + ca] : 0.f;
        v[1] = (raok && cbok) ? base[(ra << 6) + cc] : 0.f;
        v[2] = (rbok && caok) ? base[(rb << 6) + ca] : 0.f;
        v[3] = (rbok && cbok) ? base[(rb << 6) + cc] : 0.f;

        #pragma unroll
        for (int uv = 0; uv < 4; ++uv) {
            u64 vp = packff(v[uv], v[uv]);
            const ulonglong2* W = (const ulonglong2*)(sW + ((p * 32 + ci) * 4 + uv) * 16);
            ulonglong2 wA = W[0], wB = W[1], wC = W[2], wD = W[3];
            acc[0] = ffma2(wA.x, vp, acc[0]);
            acc[1] = ffma2(wA.y, vp, acc[1]);
            acc[2] = ffma2(wB.x, vp, acc[2]);
            acc[3] = ffma2(wB.y, vp, acc[3]);
            acc[4] = ffma2(wC.x, vp, acc[4]);
            acc[5] = ffma2(wC.y, vp, acc[5]);
            acc[6] = ffma2(wD.x, vp, acc[6]);
            acc[7] = ffma2(wD.y, vp, acc[7]);
        }
    }

    float* dst = g_gg + ((b * 16) << 14) + (y << 7) + x;
    #pragma unroll
    for (int q = 0; q < 8; ++q) {
        float2 m = unpackff(acc[q]);
        float lo = m.x + sb[2 * q];
        float hi = m.y + sb[2 * q + 1];
        dst[(2 * q) << 14]     = lo * normcdff(lo);
        dst[(2 * q + 1) << 14] = hi * normcdff(hi);
    }
}

// ---------------------------------------------------------------------------
// K5: up2 + conv d2 (parity-folded) + clip. Thread = (b,y,x) in 256x256.
// ---------------------------------------------------------------------------
__global__ void __launch_bounds__(256) k5_dec2(const float* __restrict__ bias,
                                               float* __restrict__ out) {
    __shared__ __align__(16) float sW[256];
    int tid = threadIdx.x;
    sW[tid] = g_Wf2[tid];
    __syncthreads();

    int lin = blockIdx.x * 256 + tid;
    int x = lin & 255, y = (lin >> 8) & 255, b = lin >> 16;
    int p = (y & 1) * 2 + (x & 1);
    int ra = (y - 1) >> 1, rb = (y + 1) >> 1;
    int ca = (x - 1) >> 1, cc = (x + 1) >> 1;
    bool raok = y > 0, rbok = rb < 128, caok = x > 0, cbok = cc < 128;

    float s = 0.f;
    #pragma unroll
    for (int ci = 0; ci < 16; ++ci) {
        const float* base = g_gg + ((b * 16 + ci) << 14);
        float v00 = (raok && caok) ? base[(ra << 7) + ca] : 0.f;
        float v01 = (raok && cbok) ? base[(ra << 7) + cc] : 0.f;
        float v10 = (rbok && caok) ? base[(rb << 7) + ca] : 0.f;
        float v11 = (rbok && cbok) ? base[(rb << 7) + cc] : 0.f;
        float4 wq = *((const float4*)(sW + (p * 16 + ci) * 4));
        s = fmaf(wq.x, v00, s);
        s = fmaf(wq.y, v01, s);
        s = fmaf(wq.z, v10, s);
        s = fmaf(wq.w, v11, s);
    }
    s += __ldg(bias);
    out[(b << 16) + (y << 8) + x] = fminf(fmaxf(s, -1.f), 1.f);
}

// ---------------------------------------------------------------------------
// K6: final commit-loss reduction (deterministic tree over 512 partials).
// ---------------------------------------------------------------------------
__global__ void __launch_bounds__(256) k6_loss(float* __restrict__ out) {
    __shared__ float sm[256];
    int tid = threadIdx.x;
    sm[tid] = g_part[tid] + g_part[tid + 256];
    __syncthreads();
    #pragma unroll
    for (int o = 128; o > 0; o >>= 1) {
        if (tid < o) sm[tid] += sm[tid + o];
        __syncthreads();
    }
    if (tid == 0) out[LOSS_OFF] = sm[0] * (1.0f / 4194304.0f);
}

// ---------------------------------------------------------------------------
extern "C" void kernel_launch(void* const* d_in, const int* in_sizes, int n_in,
                              void* d_out, int out_size) {
    const float* x   = (const float*)d_in[0];
    const float* e1w = (const float*)d_in[1];
    const float* e1b = (const float*)d_in[2];
    const float* e2w = (const float*)d_in[3];
    const float* e2b = (const float*)d_in[4];
    const float* cb  = (const float*)d_in[5];
    const float* d1w = (const float*)d_in[6];
    const float* d1b = (const float*)d_in[7];
    const float* d2w = (const float*)d_in[8];
    const float* d2b = (const float*)d_in[9];
    float* out = (float*)d_out;

    k0_setup<<<99, 256>>>(cb, d1w, d2w);
    k1_conv1<<<2048, 256>>>(x, e1w, e1b);
    k2_conv2<<<1024, 256>>>(e2w, e2b);
    k3_vq<<<512, 256>>>(cb, out);
    k4_dec1<<<2048, 256>>>(d1b);
    k5_dec2<<<8192, 256>>>(d2b, out);
    k6_loss<<<1, 256>>>(out);
}

// round 3
// speedup vs baseline: 2.3764x; 1.2138x over previous
#include <cuda_runtime.h>
#include <math.h>

// ---------------------------------------------------------------------------
// SimpleVQAutoEncoder on GB300 — fp32 SIMT + packed fma.rn.f32x2 (FFMA2)
//
//   K0: setup (codebook transpose+half-norms, parity-folded decoder weights)
//   K1: conv1(1->16,3x3,SAME) + maxpool2 + gelu        -> g_h1 [32,16,128,128]
//   K2: conv2(16->32,3x3,SAME) + maxpool2 (FFMA2)      -> g_h2 [32,32,64,64]
//   K3: VQ argmin 512 codes, 2 tokens/thread (FFMA2)   -> g_hq, indices, g_part
//   K4: up2 + conv d1(32->16) folded (FFMA2, uniform-p)-> g_gg [32,16,128,128]
//   K5: up2 + conv d2(16->1)  folded + clip (uniform-p)-> out y
//   K6: reduce commit-loss partials                    -> out[last]
//
// Output layout (float32): [ y (32*256*256) | indices (32*64*64) | loss (1) ]
// ---------------------------------------------------------------------------

#define IDX_OFF   2097152
#define LOSS_OFF  2228224

typedef unsigned long long u64;

__device__ __forceinline__ u64 ffma2(u64 a, u64 b, u64 c) {
    u64 d;
    asm("fma.rn.f32x2 %0, %1, %2, %3;" : "=l"(d) : "l"(a), "l"(b), "l"(c));
    return d;
}
__device__ __forceinline__ u64 packff(float lo, float hi) {
    u64 d;
    asm("mov.b64 %0, {%1, %2};" : "=l"(d) : "f"(lo), "f"(hi));
    return d;
}
__device__ __forceinline__ float2 unpackff(u64 v) {
    float lo, hi;
    asm("mov.b64 {%0, %1}, %2;" : "=f"(lo), "=f"(hi) : "l"(v));
    return make_float2(lo, hi);
}

// Intermediates (device globals: no allocation allowed)
__device__ float g_h1[32 * 16 * 128 * 128];   // 33.5 MB
__device__ float g_h2[32 * 32 * 64 * 64];     // 16.8 MB
__device__ float g_hq[32 * 32 * 64 * 64];     // 16.8 MB
__device__ float g_gg[32 * 16 * 128 * 128];   // 33.5 MB
__device__ float g_cbT[32 * 512];             // transposed codebook [c][k]
__device__ float g_cnh[512];                  // 0.5*||codebook_k||^2
__device__ float g_Wf1t[4 * 32 * 4 * 16];     // folded d1 [p][ci][uv][c]
__device__ float g_Wf2[4 * 16 * 4];           // folded d2 [p][ci][uv]
__device__ float g_part[512];                 // commit-loss partials

// ---------------------------------------------------------------------------
// K0: setup. Nearest-up2 folding: output (y,x) reads a 2x2 hq patch; the 3x3
// taps collapse per output parity (py,px) onto the 4 corners.
// ---------------------------------------------------------------------------
__global__ void __launch_bounds__(256) k0_setup(const float* __restrict__ cb,
                                                const float* __restrict__ d1w,
                                                const float* __restrict__ d2w) {
    int t = blockIdx.x * 256 + threadIdx.x;
    if (t < 8192) {
        // g_Wf1t[((p*32+ci)*4+uv)*16 + c]
        int c = t & 15, uv = (t >> 4) & 3, ci = (t >> 6) & 31, p = t >> 11;
        int py = p >> 1, px = p & 1, u = uv >> 1, v = uv & 1;
        float s = 0.f;
        #pragma unroll
        for (int dy = 0; dy < 3; ++dy) {
            int ug = (py == 0) ? (dy >= 1) : (dy >= 2);
            if (ug != u) continue;
            #pragma unroll
            for (int dx = 0; dx < 3; ++dx) {
                int vg = (px == 0) ? (dx >= 1) : (dx >= 2);
                if (vg != v) continue;
                s += d1w[((c * 32 + ci) * 3 + dy) * 3 + dx];
            }
        }
        g_Wf1t[t] = s;
    } else if (t < 8704) {
        int k = t - 8192;
        float s = 0.f;
        #pragma unroll
        for (int c = 0; c < 32; ++c) { float v = cb[k * 32 + c]; s = fmaf(v, v, s); }
        g_cnh[k] = 0.5f * s;
    } else if (t < 8960) {
        int e = t - 8704;
        int uv = e & 3, ci = (e >> 2) & 15, p = e >> 6;
        int py = p >> 1, px = p & 1, u = uv >> 1, v = uv & 1;
        float s = 0.f;
        #pragma unroll
        for (int dy = 0; dy < 3; ++dy) {
            int ug = (py == 0) ? (dy >= 1) : (dy >= 2);
            if (ug != u) continue;
            #pragma unroll
            for (int dx = 0; dx < 3; ++dx) {
                int vg = (px == 0) ? (dx >= 1) : (dx >= 2);
                if (vg != v) continue;
                s += d2w[ci * 9 + dy * 3 + dx];
            }
        }
        g_Wf2[(p * 16 + ci) * 4 + uv] = s;
    } else if (t < 25344) {
        int e = t - 8960;
        int c = e >> 9, k = e & 511;
        g_cbT[c * 512 + k] = cb[k * 32 + c];
    }
}

// ---------------------------------------------------------------------------
// K1: conv1 + maxpool2 + exact gelu. Thread = (b, i, j) pooled pixel, 16 ch.
// ---------------------------------------------------------------------------
__global__ void __launch_bounds__(256) k1_conv1(const float* __restrict__ x,
                                                const float* __restrict__ w,
                                                const float* __restrict__ bias) {
    __shared__ float sw[144];
    __shared__ float sb[16];
    int tid = threadIdx.x;
    if (tid < 144) sw[tid] = __ldg(w + tid);
    if (tid < 16)  sb[tid] = __ldg(bias + tid);
    __syncthreads();

    int lin = blockIdx.x * 256 + tid;
    int j = lin & 127, i = (lin >> 7) & 127, b = lin >> 14;
    const float* xb = x + (b << 16);

    float xv[4][4];
    #pragma unroll
    for (int r = 0; r < 4; ++r) {
        int ry = 2 * i - 1 + r;
        bool rok = (unsigned)ry < 256u;
        #pragma unroll
        for (int cc = 0; cc < 4; ++cc) {
            int cx = 2 * j - 1 + cc;
            xv[r][cc] = (rok && (unsigned)cx < 256u) ? __ldg(xb + ry * 256 + cx) : 0.f;
        }
    }

    #pragma unroll
    for (int c = 0; c < 16; ++c) {
        float wv[9];
        #pragma unroll
        for (int k = 0; k < 9; ++k) wv[k] = sw[c * 9 + k];
        float m = -1e30f;
        #pragma unroll
        for (int py = 0; py < 2; ++py)
            #pragma unroll
            for (int px = 0; px < 2; ++px) {
                float s = 0.f;
                #pragma unroll
                for (int dy = 0; dy < 3; ++dy)
                    #pragma unroll
                    for (int dx = 0; dx < 3; ++dx)
                        s = fmaf(wv[dy * 3 + dx], xv[py + dy][px + dx], s);
                m = fmaxf(m, s);
            }
        m += sb[c];
        g_h1[((b * 16 + c) << 14) + (i << 7) + j] = m * normcdff(m);
    }
}

// ---------------------------------------------------------------------------
// K2: conv2(16->32) + maxpool2, FFMA2 on channel pairs, prepacked patch.
// Thread = (b, half, i, j): 16 output channels, 4x4 patch reused across the
// 4 pool quadrants. half is uniform per block.
// ---------------------------------------------------------------------------
__global__ void __launch_bounds__(128) k2_conv2(const float* __restrict__ w,
                                                const float* __restrict__ bias) {
    __shared__ __align__(16) float swt[2304];  // [ci*9+tap][16c]
    __shared__ float sb[16];
    int tid = threadIdx.x;
    int lin = blockIdx.x * 128 + tid;
    int j = lin & 63, i = (lin >> 6) & 63, half = (lin >> 12) & 1, b = lin >> 13;

    for (int t = tid; t < 2304; t += 128) {
        int ci = t / 144, r = t - ci * 144;
        int tap = r >> 4, c = r & 15;
        swt[t] = __ldg(w + (half * 16 + c) * 144 + ci * 9 + tap);
    }
    if (tid < 16) sb[tid] = __ldg(bias + half * 16 + tid);
    __syncthreads();

    int ry[4], cx[4];
    bool rok[4], cok[4];
    #pragma unroll
    for (int r = 0; r < 4; ++r) {
        ry[r] = 2 * i - 1 + r; rok[r] = (unsigned)ry[r] < 128u;
        cx[r] = 2 * j - 1 + r; cok[r] = (unsigned)cx[r] < 128u;
    }

    u64 acc[4][8];
    #pragma unroll
    for (int p = 0; p < 4; ++p)
        #pragma unroll
        for (int q = 0; q < 8; ++q) acc[p][q] = 0ull;

    #pragma unroll 1
    for (int ci = 0; ci < 16; ++ci) {
        const float* src = g_h1 + ((b * 16 + ci) << 14);
        u64 patch[4][4];
        #pragma unroll
        for (int r = 0; r < 4; ++r)
            #pragma unroll
            for (int cc = 0; cc < 4; ++cc) {
                float v = (rok[r] && cok[cc]) ? src[(ry[r] << 7) + cx[cc]] : 0.f;
                patch[r][cc] = packff(v, v);
            }

        #pragma unroll
        for (int dy = 0; dy < 3; ++dy)
            #pragma unroll
            for (int dx = 0; dx < 3; ++dx) {
                const ulonglong2* W2 =
                    (const ulonglong2*)(swt + (ci * 9 + dy * 3 + dx) * 16);
                ulonglong2 wA = W2[0], wB = W2[1], wC = W2[2], wD = W2[3];
                #pragma unroll
                for (int p = 0; p < 4; ++p) {
                    u64 vp = patch[(p >> 1) + dy][(p & 1) + dx];
                    acc[p][0] = ffma2(wA.x, vp, acc[p][0]);
                    acc[p][1] = ffma2(wA.y, vp, acc[p][1]);
                    acc[p][2] = ffma2(wB.x, vp, acc[p][2]);
                    acc[p][3] = ffma2(wB.y, vp, acc[p][3]);
                    acc[p][4] = ffma2(wC.x, vp, acc[p][4]);
                    acc[p][5] = ffma2(wC.y, vp, acc[p][5]);
                    acc[p][6] = ffma2(wD.x, vp, acc[p][6]);
                    acc[p][7] = ffma2(wD.y, vp, acc[p][7]);
                }
            }
    }

    float* dst = g_h2 + ((b * 32 + half * 16) << 12) + (i << 6) + j;
    #pragma unroll
    for (int q = 0; q < 8; ++q) {
        float2 m0 = unpackff(acc[0][q]);
        float2 m1 = unpackff(acc[1][q]);
        float2 m2 = unpackff(acc[2][q]);
        float2 m3 = unpackff(acc[3][q]);
        float lo = fmaxf(fmaxf(m0.x, m1.x), fmaxf(m2.x, m3.x)) + sb[2 * q];
        float hi = fmaxf(fmaxf(m0.y, m1.y), fmaxf(m2.y, m3.y)) + sb[2 * q + 1];
        dst[(2 * q) << 12]     = lo;
        dst[(2 * q + 1) << 12] = hi;
    }
}

// ---------------------------------------------------------------------------
// K3: VQ. 2 tokens/thread, codebook [c][k] streamed via smem chunks, code
// pairs packed into f32x2 lanes. score = f.c - 0.5||c||^2 maximized.
// Ascending-k compare with strict '>' keeps first max (argmin semantics).
// ---------------------------------------------------------------------------
__global__ void __launch_bounds__(128) k3_vq(const float* __restrict__ cb,
                                             float* __restrict__ out) {
    __shared__ __align__(16) float sCb[32 * 128];  // chunk [c][128]
    __shared__ float sCn[128];
    int tid = threadIdx.x;
    int t0 = blockIdx.x * 256 + tid;
    int t1 = t0 + 128;
    int b = t0 >> 12, ij0 = t0 & 4095, ij1 = t1 & 4095;  // same image

    const float* h2b = g_h2 + (b << 17);
    float fA[32], fB[32];
    #pragma unroll
    for (int c = 0; c < 32; ++c) {
        fA[c] = h2b[(c << 12) + ij0];
        fB[c] = h2b[(c << 12) + ij1];
    }

    float bestA = -1e30f, bestB = -1e30f;
    int bkA = 0, bkB = 0;

    #pragma unroll 1
    for (int ch = 0; ch < 4; ++ch) {
        __syncthreads();
        for (int t = tid; t < 4096; t += 128) {
            int c = t >> 7, kk = t & 127;
            sCb[t] = g_cbT[c * 512 + ch * 128 + kk];
        }
        sCn[tid] = g_cnh[ch * 128 + tid];
        __syncthreads();

        #pragma unroll 1
        for (int g = 0; g < 16; ++g) {
            u64 sA[4] = {0ull, 0ull, 0ull, 0ull};
            u64 sB[4] = {0ull, 0ull, 0ull, 0ull};
            #pragma unroll
            for (int c = 0; c < 32; ++c) {
                u64 fpA = packff(fA[c], fA[c]);
                u64 fpB = packff(fB[c], fB[c]);
                const ulonglong2* W = (const ulonglong2*)(sCb + c * 128 + g * 8);
                ulonglong2 w0 = W[0], w1 = W[1];
                sA[0] = ffma2(w0.x, fpA, sA[0]);
                sA[1] = ffma2(w0.y, fpA, sA[1]);
                sA[2] = ffma2(w1.x, fpA, sA[2]);
                sA[3] = ffma2(w1.y, fpA, sA[3]);
                sB[0] = ffma2(w0.x, fpB, sB[0]);
                sB[1] = ffma2(w0.y, fpB, sB[1]);
                sB[2] = ffma2(w1.x, fpB, sB[2]);
                sB[3] = ffma2(w1.y, fpB, sB[3]);
            }
            int kbase = ch * 128 + g * 8;
            #pragma unroll
            for (int q = 0; q < 4; ++q) {
                float cn0 = sCn[g * 8 + 2 * q], cn1 = sCn[g * 8 + 2 * q + 1];
                float2 a = unpackff(sA[q]);
                float va0 = a.x - cn0;
                if (va0 > bestA) { bestA = va0; bkA = kbase + 2 * q; }
                float va1 = a.y - cn1;
                if (va1 > bestA) { bestA = va1; bkA = kbase + 2 * q + 1; }
                float2 bb = unpackff(sB[q]);
                float vb0 = bb.x - cn0;
                if (vb0 > bestB) { bestB = vb0; bkB = kbase + 2 * q; }
                float vb1 = bb.y - cn1;
                if (vb1 > bestB) { bestB = vb1; bkB = kbase + 2 * q + 1; }
            }
        }
    }

    out[IDX_OFF + t0] = (float)bkA;
    out[IDX_OFF + t1] = (float)bkB;

    float part = 0.f;
    #pragma unroll
    for (int c = 0; c < 32; ++c) {
        float qA = __ldg(cb + bkA * 32 + c);
        float dA = qA - fA[c];
        part = fmaf(dA, dA, part);
        g_hq[(b << 17) + (c << 12) + ij0] = qA;
        float qB = __ldg(cb + bkB * 32 + c);
        float dB = qB - fB[c];
        part = fmaf(dB, dB, part);
        g_hq[(b << 17) + (c << 12) + ij1] = qB;
    }

    __shared__ float ws[4];
    #pragma unroll
    for (int o = 16; o > 0; o >>= 1)
        part += __shfl_down_sync(0xffffffffu, part, o);
    if ((tid & 31) == 0) ws[tid >> 5] = part;
    __syncthreads();
    if (tid == 0) {
        float s = 0.f;
        #pragma unroll
        for (int q = 0; q < 4; ++q) s += ws[q];
        g_part[blockIdx.x] = s;
    }
}

// ---------------------------------------------------------------------------
// K4: up2 + conv d1 (parity-folded) + gelu, FFMA2 channel pairs.
// Warp-parity mapping: each warp covers one x-parity -> p is warp-uniform ->
// weight LDS is a broadcast (no 4-phase conflicts).
// ---------------------------------------------------------------------------
__global__ void __launch_bounds__(256) k4_dec1(const float* __restrict__ bias) {
    __shared__ __align__(16) float sW[8192];  // [p][ci][uv][16c]
    __shared__ float sb[16];
    int tid = threadIdx.x;
    for (int t = tid; t < 8192; t += 256) sW[t] = g_Wf1t[t];
    if (tid < 16) sb[tid] = __ldg(bias + tid);
    __syncthreads();

    int lin = blockIdx.x * 256 + tid;
    int lane = lin & 31;
    int wq = (lin >> 5) & 3;          // warp quadrant within row
    int y = (lin >> 7) & 127;
    int b = lin >> 14;
    int px = wq & 1;                  // warp-uniform
    int xi = lane + ((wq >> 1) << 5); // 0..63
    int x = 2 * xi + px;

    int p = (y & 1) * 2 + px;         // warp-uniform
    int ra = (y - 1) >> 1, rb = (y + 1) >> 1;
    int ca = xi - 1 + px, cc = xi;    // (x-1)>>1, (x+1)>>1 rewritten
    // px=0: ca=xi-1, cc=xi ; px=1: ca=xi, cc=xi (x+1 may hit 128)
    int cb2 = (x + 1) >> 1;
    bool raok = y > 0, rbok = rb < 64, caok = x > 0, cbok = cb2 < 64;
    ca = (x - 1) >> 1; cc = cb2;

    u64 acc[8];
    #pragma unroll
    for (int q = 0; q < 8; ++q) acc[q] = 0ull;

    #pragma unroll 1
    for (int ci = 0; ci < 32; ++ci) {
        const float* base = g_hq + (b << 17) + (ci << 12);
        float v[4];
        v[0] = (raok && caok) ? base[(ra << 6) + ca] : 0.f;
        v[1] = (raok && cbok) ? base[(ra << 6) + cc] : 0.f;
        v[2] = (rbok && caok) ? base[(rb << 6) + ca] : 0.f;
        v[3] = (rbok && cbok) ? base[(rb << 6) + cc] : 0.f;

        #pragma unroll
        for (int uv = 0; uv < 4; ++uv) {
            u64 vp = packff(v[uv], v[uv]);
            const ulonglong2* W = (const ulonglong2*)(sW + ((p * 32 + ci) * 4 + uv) * 16);
            ulonglong2 wA = W[0], wB = W[1], wC = W[2], wD = W[3];
            acc[0] = ffma2(wA.x, vp, acc[0]);
            acc[1] = ffma2(wA.y, vp, acc[1]);
            acc[2] = ffma2(wB.x, vp, acc[2]);
            acc[3] = ffma2(wB.y, vp, acc[3]);
            acc[4] = ffma2(wC.x, vp, acc[4]);
            acc[5] = ffma2(wC.y, vp, acc[5]);
            acc[6] = ffma2(wD.x, vp, acc[6]);
            acc[7] = ffma2(wD.y, vp, acc[7]);
        }
    }

    float* dst = g_gg + ((b * 16) << 14) + (y << 7) + x;
    #pragma unroll
    for (int q = 0; q < 8; ++q) {
        float2 m = unpackff(acc[q]);
        float lo = m.x + sb[2 * q];
        float hi = m.y + sb[2 * q + 1];
        dst[(2 * q) << 14]     = lo * normcdff(lo);
        dst[(2 * q + 1) << 14] = hi * normcdff(hi);
    }
}

// ---------------------------------------------------------------------------
// K5: up2 + conv d2 (parity-folded) + clip, warp-parity mapping (uniform p).
// ---------------------------------------------------------------------------
__global__ void __launch_bounds__(256) k5_dec2(const float* __restrict__ bias,
                                               float* __restrict__ out) {
    __shared__ __align__(16) float sW[256];
    int tid = threadIdx.x;
    sW[tid] = g_Wf2[tid];
    __syncthreads();

    int lin = blockIdx.x * 256 + tid;
    int lane = lin & 31;
    int wq = (lin >> 5) & 7;           // 8 warps per 256-px row
    int y = (lin >> 8) & 255;
    int b = lin >> 16;
    int px = wq & 1;                   // warp-uniform
    int xi = lane + ((wq >> 1) << 5);  // 0..127
    int x = 2 * xi + px;

    int p = (y & 1) * 2 + px;          // warp-uniform
    int ra = (y - 1) >> 1, rb = (y + 1) >> 1;
    int ca = (x - 1) >> 1, cc = (x + 1) >> 1;
    bool raok = y > 0, rbok = rb < 128, caok = x > 0, cbok = cc < 128;

    float s = 0.f;
    #pragma unroll
    for (int ci = 0; ci < 16; ++ci) {
        const float* base = g_gg + ((b * 16 + ci) << 14);
        float v00 = (raok && caok) ? base[(ra << 7) + ca] : 0.f;
        float v01 = (raok && cbok) ? base[(ra << 7) + cc] : 0.f;
        float v10 = (rbok && caok) ? base[(rb << 7) + ca] : 0.f;
        float v11 = (rbok && cbok) ? base[(rb << 7) + cc] : 0.f;
        float4 wqv = *((const float4*)(sW + (p * 16 + ci) * 4));
        s = fmaf(wqv.x, v00, s);
        s = fmaf(wqv.y, v01, s);
        s = fmaf(wqv.z, v10, s);
        s = fmaf(wqv.w, v11, s);
    }
    s += __ldg(bias);
    out[(b << 16) + (y << 8) + x] = fminf(fmaxf(s, -1.f), 1.f);
}

// ---------------------------------------------------------------------------
// K6: final commit-loss reduction (deterministic tree over 512 partials).
// ---------------------------------------------------------------------------
__global__ void __launch_bounds__(256) k6_loss(float* __restrict__ out) {
    __shared__ float sm[256];
    int tid = threadIdx.x;
    sm[tid] = g_part[tid] + g_part[tid + 256];
    __syncthreads();
    #pragma unroll
    for (int o = 128; o > 0; o >>= 1) {
        if (tid < o) sm[tid] += sm[tid + o];
        __syncthreads();
    }
    if (tid == 0) out[LOSS_OFF] = sm[0] * (1.0f / 4194304.0f);
}

// ---------------------------------------------------------------------------
extern "C" void kernel_launch(void* const* d_in, const int* in_sizes, int n_in,
                              void* d_out, int out_size) {
    const float* x   = (const float*)d_in[0];
    const float* e1w = (const float*)d_in[1];
    const float* e1b = (const float*)d_in[2];
    const float* e2w = (const float*)d_in[3];
    const float* e2b = (const float*)d_in[4];
    const float* cb  = (const float*)d_in[5];
    const float* d1w = (const float*)d_in[6];
    const float* d1b = (const float*)d_in[7];
    const float* d2w = (const float*)d_in[8];
    const float* d2b = (const float*)d_in[9];
    float* out = (float*)d_out;

    k0_setup<<<99, 256>>>(cb, d1w, d2w);
    k1_conv1<<<2048, 256>>>(x, e1w, e1b);
    k2_conv2<<<2048, 128>>>(e2w, e2b);
    k3_vq<<<512, 128>>>(cb, out);
    k4_dec1<<<2048, 256>>>(d1b);
    k5_dec2<<<8192, 256>>>(d2b, out);
    k6_loss<<<1, 256>>>(out);
}